// round 15
// baseline (speedup 1.0000x reference)
#include <cuda_runtime.h>
#include <cstdint>

// CoordsToNRF: out[b, p] = atoms_flat[p] * (AU2KCALMOLA / MAX_NRF) / ||c_i - c_j||^2
// p = i*(i-1)/2 + j over the strict lower triangle of 128 atoms. B=2048, NC2=8128.
//
// Round-15: 64-wide j-tiles (2 j's per thread) x batch-pair f32x2 = 128
// outputs per warp-row. Two tiles only (j0=0: rows i=1..127, j0=64: rows
// i=65..127) -> 190 flat rows, 24/23 per warp, consecutive-i sweep (dense
// in-order stores). C++ predicated stores, coords pre-scaled, one address
// register with +32 / +NC2 / +NC2+32 immediate offsets.

#define N_ATOMS 128
#define NC2     8128
#define BLOCK_THREADS 256      // 8 warps, one batch PAIR per block

// sqrt(1 / (627.5095 * 0.529177 / 100.0)):
#define COORD_PRESCALE 0.5487683f

typedef unsigned long long u64;

__device__ __forceinline__ u64 f2_add(u64 a, u64 b) {
    u64 r; asm("add.rn.f32x2 %0, %1, %2;" : "=l"(r) : "l"(a), "l"(b)); return r;
}
__device__ __forceinline__ u64 f2_mul(u64 a, u64 b) {
    u64 r; asm("mul.rn.f32x2 %0, %1, %2;" : "=l"(r) : "l"(a), "l"(b)); return r;
}
__device__ __forceinline__ u64 f2_fma(u64 a, u64 b, u64 c) {
    u64 r; asm("fma.rn.f32x2 %0, %1, %2, %3;" : "=l"(r) : "l"(a), "l"(b), "l"(c)); return r;
}
__device__ __forceinline__ float2 f2_lohi(u64 v) {
    float2 f; asm("mov.b64 {%0, %1}, %2;" : "=f"(f.x), "=f"(f.y) : "l"(v)); return f;
}

__global__ __launch_bounds__(BLOCK_THREADS, 6)
void coords_to_nrf_kernel(const float* __restrict__ coords,
                          const float* __restrict__ atoms_flat,
                          float* __restrict__ out) {
    // Packed pair coords (pre-scaled): atom a -> {x0,x1,y0,y1,z0,z1,pad,pad}.
    __shared__ __align__(16) float sc[N_ATOMS * 8];

    const int warp = threadIdx.x >> 5;    // 0..7 -> flat row chunk
    const int lane = threadIdx.x & 31;
    const int bg   = blockIdx.x;          // batch pair index

    // ---- Stage batch pair, pre-scaled ----
    const float* cb = coords + (size_t)bg * 2 * (N_ATOMS * 3);
    #pragma unroll
    for (int idx = threadIdx.x; idx < 2 * N_ATOMS * 3; idx += BLOCK_THREADS) {
        const int q   = idx / (N_ATOMS * 3);
        const int rem = idx - q * (N_ATOMS * 3);
        const int a   = rem / 3;
        const int d   = rem - a * 3;
        sc[a * 8 + d * 2 + q] = cb[idx] * COORD_PRESCALE;
    }
    __syncthreads();

    const u64 S = 0x8000000080000000ull;   // packed f32x2 sign flip

    // Flat rows [0,190): tile0 (j0=0) rows r=0..126 (i=1+r),
    //                    tile1 (j0=64) rows r=127..189 (i=r-62).
    // Chunks: 24,24,24,24,24,24,23,23.
    const int r0 = (warp < 6) ? 24 * warp : 144 + 23 * (warp - 6);
    const int r1 = r0 + ((warp < 6) ? 24 : 23);

    float* ob = out + (size_t)bg * 2 * NC2;

    // ================= Segment: tile0 (j0 = 0) =================
    {
        const int a = r0;
        const int b = (r1 < 127) ? r1 : 127;
        if (a < b) {
            const int ja = lane;
            const ulonglong2 cjaxy = *reinterpret_cast<const ulonglong2*>(&sc[ja * 8]);
            const u64        cjaz  = *reinterpret_cast<const u64*>(&sc[ja * 8 + 4]);
            const ulonglong2 cjbxy = *reinterpret_cast<const ulonglong2*>(&sc[(ja + 32) * 8]);
            const u64        cjbz  = *reinterpret_cast<const u64*>(&sc[(ja + 32) * 8 + 4]);
            const u64 nax = cjaxy.x ^ S, nay = cjaxy.y ^ S, naz = cjaz ^ S;
            const u64 nbx = cjbxy.x ^ S, nby = cjbxy.y ^ S, nbz = cjbz ^ S;

            int i = 1 + a;
            const int i_hi  = 1 + b;
            const int i_mid = (i_hi < 64) ? i_hi : ((i > 64) ? i : 64);
            int pbase = ((i * (i - 1)) >> 1) + lane;   // p for j = lane

            // -- partial rows: i < 64, both halves predicated --
            #pragma unroll 2
            for (; i < i_mid; i++) {
                const ulonglong2 cixy = *reinterpret_cast<const ulonglong2*>(&sc[i * 8]);
                const u64        ciz  = *reinterpret_cast<const u64*>(&sc[i * 8 + 4]);

                const u64 dxa = f2_add(cixy.x, nax);
                const u64 dya = f2_add(cixy.y, nay);
                const u64 dza = f2_add(ciz,    naz);
                const u64 d2a = f2_fma(dza, dza, f2_fma(dya, dya, f2_mul(dxa, dxa)));
                const u64 dxb = f2_add(cixy.x, nbx);
                const u64 dyb = f2_add(cixy.y, nby);
                const u64 dzb = f2_add(ciz,    nbz);
                const u64 d2b = f2_fma(dzb, dzb, f2_fma(dyb, dyb, f2_mul(dxb, dxb)));

                const float2 A = f2_lohi(d2a);
                const float2 B = f2_lohi(d2b);

                const int p = pbase;                    // <= T(63)+31: in-bounds
                const float ava = __ldg(&atoms_flat[p]);
                const float avb = __ldg(&atoms_flat[p + 32]);
                float* o = ob + p;
                if (lane < i) {                         // j = lane valid
                    o[0]   = __fdividef(ava, A.x);
                    o[NC2] = __fdividef(ava, A.y);
                }
                if (lane + 32 < i) {                    // j = lane+32 valid
                    o[32]       = __fdividef(avb, B.x);
                    o[NC2 + 32] = __fdividef(avb, B.y);
                }
                pbase += i;
            }

            // -- full rows: i >= 64, all 64 j's valid --
            #pragma unroll 2
            for (; i < i_hi; i++) {
                const ulonglong2 cixy = *reinterpret_cast<const ulonglong2*>(&sc[i * 8]);
                const u64        ciz  = *reinterpret_cast<const u64*>(&sc[i * 8 + 4]);

                const u64 dxa = f2_add(cixy.x, nax);
                const u64 dya = f2_add(cixy.y, nay);
                const u64 dza = f2_add(ciz,    naz);
                const u64 d2a = f2_fma(dza, dza, f2_fma(dya, dya, f2_mul(dxa, dxa)));
                const u64 dxb = f2_add(cixy.x, nbx);
                const u64 dyb = f2_add(cixy.y, nby);
                const u64 dzb = f2_add(ciz,    nbz);
                const u64 d2b = f2_fma(dzb, dzb, f2_fma(dyb, dyb, f2_mul(dxb, dxb)));

                const float2 A = f2_lohi(d2a);
                const float2 B = f2_lohi(d2b);

                const int p = pbase;
                const float ava = __ldg(&atoms_flat[p]);
                const float avb = __ldg(&atoms_flat[p + 32]);
                float* o = ob + p;
                o[0]        = __fdividef(ava, A.x);
                o[NC2]      = __fdividef(ava, A.y);
                o[32]       = __fdividef(avb, B.x);
                o[NC2 + 32] = __fdividef(avb, B.y);
                pbase += i;
            }
        }
    }

    // ================= Segment: tile1 (j0 = 64), all rows partial =========
    {
        const int a = (r0 > 127) ? r0 : 127;
        const int b = r1;
        if (a < b) {
            const int ja = 64 + lane;
            const ulonglong2 cjaxy = *reinterpret_cast<const ulonglong2*>(&sc[ja * 8]);
            const u64        cjaz  = *reinterpret_cast<const u64*>(&sc[ja * 8 + 4]);
            const ulonglong2 cjbxy = *reinterpret_cast<const ulonglong2*>(&sc[(ja + 32) * 8]);
            const u64        cjbz  = *reinterpret_cast<const u64*>(&sc[(ja + 32) * 8 + 4]);
            const u64 nax = cjaxy.x ^ S, nay = cjaxy.y ^ S, naz = cjaz ^ S;
            const u64 nbx = cjbxy.x ^ S, nby = cjbxy.y ^ S, nbz = cjbz ^ S;

            int i = a - 62;                            // i in [65, 128)
            const int i_hi = b - 62;
            int pbase = ((i * (i - 1)) >> 1) + 64 + lane;

            #pragma unroll 2
            for (; i < i_hi; i++) {
                const ulonglong2 cixy = *reinterpret_cast<const ulonglong2*>(&sc[i * 8]);
                const u64        ciz  = *reinterpret_cast<const u64*>(&sc[i * 8 + 4]);

                const u64 dxa = f2_add(cixy.x, nax);
                const u64 dya = f2_add(cixy.y, nay);
                const u64 dza = f2_add(ciz,    naz);
                const u64 d2a = f2_fma(dza, dza, f2_fma(dya, dya, f2_mul(dxa, dxa)));
                const u64 dxb = f2_add(cixy.x, nbx);
                const u64 dyb = f2_add(cixy.y, nby);
                const u64 dzb = f2_add(ciz,    nbz);
                const u64 d2b = f2_fma(dzb, dzb, f2_fma(dyb, dyb, f2_mul(dxb, dxb)));

                const float2 A = f2_lohi(d2a);
                const float2 B = f2_lohi(d2b);

                const int p  = pbase;                  // p <= 8096: in-bounds
                const int pb = (p + 32 < NC2) ? (p + 32) : (NC2 - 1);  // i=127 edge
                const float ava = __ldg(&atoms_flat[p]);
                const float avb = __ldg(&atoms_flat[pb]);
                float* o = ob + p;
                const int vlim = i - 64;
                if (lane < vlim) {
                    o[0]   = __fdividef(ava, A.x);
                    o[NC2] = __fdividef(ava, A.y);
                }
                if (lane + 32 < vlim) {
                    o[32]       = __fdividef(avb, B.x);
                    o[NC2 + 32] = __fdividef(avb, B.y);
                }
                pbase += i;
            }
        }
    }
}

extern "C" void kernel_launch(void* const* d_in, const int* in_sizes, int n_in,
                              void* d_out, int out_size) {
    const float* coords     = (const float*)d_in[0];  // [2048, 128, 3] f32
    const float* atoms_flat = (const float*)d_in[1];  // [8128] f32
    float* out = (float*)d_out;                       // [2048, 8128] f32

    const int batch = in_sizes[0] / (N_ATOMS * 3);    // 2048
    coords_to_nrf_kernel<<<batch / 2, BLOCK_THREADS>>>(coords, atoms_flat, out);
}

// round 16
// speedup vs baseline: 1.1807x; 1.1807x over previous
#include <cuda_runtime.h>
#include <cstdint>

// CoordsToNRF: out[b, p] = atoms_flat[p] * (AU2KCALMOLA / MAX_NRF) / ||c_i - c_j||^2
// p = i*(i-1)/2 + j over the strict lower triangle of 128 atoms. B=2048, NC2=8128.
//
// Round-16: R14 (best shape: 2-batch f32x2, flat chunks, prescaled coords,
// partial/full loop split, 32 regs) with occupancy pushed to 8 blocks/SM
// (64 warps/SM, single wave) and unroll 8 on the full-row loop for ILP.

#define N_ATOMS 128
#define NC2     8128
#define BLOCK_THREADS 256      // 8 warps, one batch PAIR per block

// sqrt(1 / (627.5095 * 0.529177 / 100.0)):
#define COORD_PRESCALE 0.5487683f

typedef unsigned long long u64;

__device__ __forceinline__ u64 f2_add(u64 a, u64 b) {
    u64 r; asm("add.rn.f32x2 %0, %1, %2;" : "=l"(r) : "l"(a), "l"(b)); return r;
}
__device__ __forceinline__ u64 f2_mul(u64 a, u64 b) {
    u64 r; asm("mul.rn.f32x2 %0, %1, %2;" : "=l"(r) : "l"(a), "l"(b)); return r;
}
__device__ __forceinline__ u64 f2_fma(u64 a, u64 b, u64 c) {
    u64 r; asm("fma.rn.f32x2 %0, %1, %2, %3;" : "=l"(r) : "l"(a), "l"(b), "l"(c)); return r;
}
__device__ __forceinline__ float2 f2_lohi(u64 v) {
    float2 f; asm("mov.b64 {%0, %1}, %2;" : "=f"(f.x), "=f"(f.y) : "l"(v)); return f;
}

__global__ __launch_bounds__(BLOCK_THREADS, 8)
void coords_to_nrf_kernel(const float* __restrict__ coords,
                          const float* __restrict__ atoms_flat,
                          float* __restrict__ out) {
    // Packed pair coords (pre-scaled): atom a -> {x0,x1,y0,y1,z0,z1,pad,pad}.
    __shared__ __align__(16) float sc[N_ATOMS * 8];

    const int warp = threadIdx.x >> 5;    // 0..7 -> row chunk
    const int lane = threadIdx.x & 31;
    const int bg   = blockIdx.x;          // batch pair index

    // ---- Stage batch pair, pre-scaled by sqrt(1/scale) ----
    const float* cb = coords + (size_t)bg * 2 * (N_ATOMS * 3);
    #pragma unroll
    for (int idx = threadIdx.x; idx < 2 * N_ATOMS * 3; idx += BLOCK_THREADS) {
        const int q   = idx / (N_ATOMS * 3);       // batch in pair
        const int rem = idx - q * (N_ATOMS * 3);
        const int a   = rem / 3;
        const int d   = rem - a * 3;
        sc[a * 8 + d * 2 + q] = cb[idx] * COORD_PRESCALE;
    }
    __syncthreads();

    const u64 S = 0x8000000080000000ull;           // packed f32x2 sign flip

    // Flat rows [0,316) split: 40,40,40,40,39,39,39,39.
    const int over = (warp > 4) ? (warp - 4) : 0;
    const int r0 = 40 * warp - over;
    const int r1 = r0 + ((warp < 4) ? 40 : 39);

    const int starts[5] = {0, 127, 222, 285, 316};

    float* ob = out + (size_t)bg * 2 * NC2;        // batch q=0 plane

    #pragma unroll
    for (int seg = 0; seg < 4; seg++) {
        const int a = (r0 > starts[seg])     ? r0 : starts[seg];
        const int b = (r1 < starts[seg + 1]) ? r1 : starts[seg + 1];
        if (a >= b) continue;

        const int j0 = seg * 32;
        const int j  = j0 + lane;

        // cj pair straight from smem as 64-bit lane pairs, negated once.
        const ulonglong2 cj_xy = *reinterpret_cast<const ulonglong2*>(&sc[j * 8]);
        const u64        cj_z  = *reinterpret_cast<const u64*>(&sc[j * 8 + 4]);
        const u64 ncjx = cj_xy.x ^ S;
        const u64 ncjy = cj_xy.y ^ S;
        const u64 ncjz = cj_z   ^ S;

        const int i0   = j0 + 1 + (a - starts[seg]);
        const int iend = i0 + (b - a);
        // Rows with i < j0+32 are partial (per-lane mask); i >= j0+32 full.
        const int im_raw = j0 + 32;
        const int im = (iend < im_raw) ? iend : ((i0 > im_raw) ? i0 : im_raw);

        int pbase = (i0 * (i0 - 1)) >> 1;

        // ---- partial rows: clamp LDG, predicated stores ----
        #pragma unroll 4
        for (int i = i0; i < im; i++) {
            const ulonglong2 cixy = *reinterpret_cast<const ulonglong2*>(&sc[i * 8]);
            const u64        ciz  = *reinterpret_cast<const u64*>(&sc[i * 8 + 4]);

            const u64 dx2 = f2_add(cixy.x, ncjx);
            const u64 dy2 = f2_add(cixy.y, ncjy);
            const u64 dz2 = f2_add(ciz,    ncjz);
            const u64 d2p = f2_fma(dz2, dz2, f2_fma(dy2, dy2, f2_mul(dx2, dx2)));
            const float2 d2 = f2_lohi(d2p);

            const int p  = pbase + j;
            const int pc = (p < NC2 - 1) ? p : (NC2 - 1);  // masked-lane safety
            const float aval = __ldg(&atoms_flat[pc]);     // scale folded in d2
            const float ra = __fdividef(aval, d2.x);        // batch 0
            const float rb = __fdividef(aval, d2.y);        // batch 1

            if (j < i) {               // bare predicated store pair -> @P STG
                ob[p]       = ra;
                ob[p + NC2] = rb;
            }
            pbase += i;
        }

        // ---- full rows: all 32 lanes valid, no clamp, no predicate ----
        #pragma unroll 8
        for (int i = im; i < iend; i++) {
            const ulonglong2 cixy = *reinterpret_cast<const ulonglong2*>(&sc[i * 8]);
            const u64        ciz  = *reinterpret_cast<const u64*>(&sc[i * 8 + 4]);

            const u64 dx2 = f2_add(cixy.x, ncjx);
            const u64 dy2 = f2_add(cixy.y, ncjy);
            const u64 dz2 = f2_add(ciz,    ncjz);
            const u64 d2p = f2_fma(dz2, dz2, f2_fma(dy2, dy2, f2_mul(dx2, dx2)));
            const float2 d2 = f2_lohi(d2p);

            const int p = pbase + j;
            const float aval = __ldg(&atoms_flat[p]);

            ob[p]       = __fdividef(aval, d2.x);
            ob[p + NC2] = __fdividef(aval, d2.y);
            pbase += i;
        }
    }
}

extern "C" void kernel_launch(void* const* d_in, const int* in_sizes, int n_in,
                              void* d_out, int out_size) {
    const float* coords     = (const float*)d_in[0];  // [2048, 128, 3] f32
    const float* atoms_flat = (const float*)d_in[1];  // [8128] f32
    float* out = (float*)d_out;                       // [2048, 8128] f32

    const int batch = in_sizes[0] / (N_ATOMS * 3);    // 2048
    coords_to_nrf_kernel<<<batch / 2, BLOCK_THREADS>>>(coords, atoms_flat, out);
}